// round 11
// baseline (speedup 1.0000x reference)
#include <cuda_runtime.h>
#include <cstdint>

#define NN 50000
#define EE 800000
#define E2 (EE + NN)
#define F0 256
#define FF 192
#define NH 3
#define HD 64
#define NC 40

// ---------------- static device scratch ----------------
__device__ __align__(128) float    g_H[NN * FF];
__device__ __align__(128) float    g_X[NN * FF];
__device__ float    g_asrc[NN * NH];
__device__ float    g_adst[NN * NH];
__device__ int      g_deg[NN];
__device__ int      g_cur[NN];
__device__ int      g_rowptr[NN + 1];
__device__ int      g_csrc[E2];

// ---------------- helpers ----------------
__device__ __forceinline__ uint32_t s2u(const void* p) {
    uint32_t a;
    asm("{ .reg .u64 t; cvta.to.shared.u64 t, %1; cvt.u32.u64 %0, t; }" : "=r"(a) : "l"(p));
    return a;
}
__device__ __forceinline__ void cp16(uint32_t s, const void* g) {
    asm volatile("cp.async.cg.shared.global [%0], [%1], 16;" :: "r"(s), "l"(g));
}
__device__ __forceinline__ void cp16z(uint32_t s, const void* g, int valid) {
    asm volatile("cp.async.cg.shared.global [%0], [%1], 16, %2;" :: "r"(s), "l"(g), "r"(valid));
}
__device__ __forceinline__ void cp_commit() { asm volatile("cp.async.commit_group;" ::: "memory"); }
template<int NPEND> __device__ __forceinline__ void cp_wait() {
    asm volatile("cp.async.wait_group %0;" :: "n"(NPEND) : "memory");
}
__device__ __forceinline__ uint32_t f2tf(float f) {
    uint32_t r;
    asm("cvt.rna.tf32.f32 %0, %1;" : "=r"(r) : "f"(f));
    return r;
}
__device__ __forceinline__ void mma_tf32(float* c, const uint32_t* a, const uint32_t* b) {
    asm volatile(
        "mma.sync.aligned.m16n8k8.row.col.f32.tf32.tf32.f32 "
        "{%0,%1,%2,%3}, {%4,%5,%6,%7}, {%8,%9}, {%0,%1,%2,%3};"
        : "+f"(c[0]), "+f"(c[1]), "+f"(c[2]), "+f"(c[3])
        : "r"(a[0]), "r"(a[1]), "r"(a[2]), "r"(a[3]), "r"(b[0]), "r"(b[1]));
}

// ---------------- tf32 mma.sync GEMM: C[M,N] = A[M,K] @ B[K,N] (+bias) ----------------
// BM=128 BN=64 BK=16, 256 threads = 8 warps (4 along M x 2 along N), warp tile 32x32.
// (identical to the round-6 kernel that measured fastest — no epilogue fusion)
#define AST 20   // As row stride (floats)
#define BST 72   // Bs row stride (floats)

__global__ void __launch_bounds__(256) gemm_mma_k(
    const float* __restrict__ A, const float* __restrict__ B, float* __restrict__ C,
    int M, int K, int N, const float* __restrict__ bias)
{
    __shared__ float As[2][128 * AST];
    __shared__ float Bs[2][16 * BST];

    int tid = threadIdx.x, wid = tid >> 5, lane = tid & 31;
    int warp_m = wid & 3, warp_n = wid >> 2;
    int m0 = blockIdx.x * 128, n0 = blockIdx.y * 64;
    int gid = lane >> 2, tig = lane & 3;

    float acc[2][4][4];
    #pragma unroll
    for (int i = 0; i < 2; i++)
        #pragma unroll
        for (int j = 0; j < 4; j++)
            #pragma unroll
            for (int t = 0; t < 4; t++) acc[i][j][t] = 0.f;

    uint32_t asb[2] = { s2u(As[0]), s2u(As[1]) };
    uint32_t bsb[2] = { s2u(Bs[0]), s2u(Bs[1]) };

    auto prefetch = [&](int st, int kt) {
        int k0 = kt * 16;
        #pragma unroll
        for (int i = 0; i < 2; i++) {
            int idx = tid + i * 256;
            int m = idx >> 2, ch = idx & 3;
            int grow = m0 + m; if (grow >= M) grow = M - 1;
            cp16(asb[st] + (uint32_t)(m * AST + ch * 4) * 4u,
                 A + (size_t)grow * K + k0 + ch * 4);
        }
        {
            int k = tid >> 4, ch = tid & 15;
            int col = n0 + ch * 4;
            int valid = (N - col) * 4;
            if (valid > 16) valid = 16;
            if (valid < 0) valid = 0;
            const float* src = B + (size_t)(k0 + k) * N + (valid > 0 ? col : 0);
            cp16z(bsb[st] + (uint32_t)(k * BST + ch * 4) * 4u, src, valid);
        }
    };

    int KT = K >> 4;
    prefetch(0, 0); cp_commit();
    prefetch(1, 1); cp_commit();

    for (int kt = 0; kt < KT; kt++) {
        int st = kt & 1;
        if (kt + 1 < KT) cp_wait<1>(); else cp_wait<0>();
        __syncthreads();

        const float* as = As[st];
        const float* bs = Bs[st];
        #pragma unroll
        for (int ks = 0; ks < 2; ks++) {
            int kk = ks * 8;
            uint32_t af[2][4], bf[4][2];
            #pragma unroll
            for (int mt = 0; mt < 2; mt++) {
                int r = warp_m * 32 + mt * 16 + gid;
                af[mt][0] = f2tf(as[r * AST + kk + tig]);
                af[mt][1] = f2tf(as[(r + 8) * AST + kk + tig]);
                af[mt][2] = f2tf(as[r * AST + kk + tig + 4]);
                af[mt][3] = f2tf(as[(r + 8) * AST + kk + tig + 4]);
            }
            #pragma unroll
            for (int nt = 0; nt < 4; nt++) {
                int c = warp_n * 32 + nt * 8 + gid;
                bf[nt][0] = f2tf(bs[(kk + tig) * BST + c]);
                bf[nt][1] = f2tf(bs[(kk + tig + 4) * BST + c]);
            }
            #pragma unroll
            for (int mt = 0; mt < 2; mt++)
                #pragma unroll
                for (int nt = 0; nt < 4; nt++)
                    mma_tf32(acc[mt][nt], af[mt], bf[nt]);
        }
        __syncthreads();
        if (kt + 2 < KT) { prefetch(st, kt + 2); cp_commit(); }
    }

    // ---- epilogue ----
    #pragma unroll
    for (int mt = 0; mt < 2; mt++) {
        #pragma unroll
        for (int nt = 0; nt < 4; nt++) {
            int col = n0 + warp_n * 32 + nt * 8 + tig * 2;
            if (col >= N) continue;
            float bx = 0.f, by = 0.f;
            if (bias) { bx = bias[col]; by = bias[col + 1]; }
            int r0 = m0 + warp_m * 32 + mt * 16 + gid;
            if (r0 < M)
                *(float2*)&C[(size_t)r0 * N + col] =
                    make_float2(acc[mt][nt][0] + bx, acc[mt][nt][1] + by);
            int r1 = r0 + 8;
            if (r1 < M)
                *(float2*)&C[(size_t)r1 * N + col] =
                    make_float2(acc[mt][nt][2] + bx, acc[mt][nt][3] + by);
        }
    }
}

// ---------------- CSR build ----------------
__global__ void zero_nodes() {
    int i = blockIdx.x * blockDim.x + threadIdx.x;
    if (i < NN) { g_deg[i] = 0; g_cur[i] = 0; }
}

__global__ void hist_k(const int* __restrict__ dst) {
    int e = blockIdx.x * blockDim.x + threadIdx.x;
    if (e >= E2) return;
    int d = (e < EE) ? dst[e] : (e - EE);
    atomicAdd(&g_deg[d], 1);
}

__global__ void scan_k() {
    __shared__ int wsum[32];
    __shared__ int carry;
    int tid = threadIdx.x, lane = tid & 31, w = tid >> 5;
    if (tid == 0) { carry = 0; g_rowptr[0] = 0; }
    __syncthreads();
    const int TILES = (NN + 1023) / 1024;
    for (int t = 0; t < TILES; t++) {
        int i = t * 1024 + tid;
        int x = (i < NN) ? g_deg[i] : 0;
        #pragma unroll
        for (int o = 1; o < 32; o <<= 1) {
            int y = __shfl_up_sync(0xffffffffu, x, o);
            if (lane >= o) x += y;
        }
        if (lane == 31) wsum[w] = x;
        __syncthreads();
        if (w == 0) {
            int v = wsum[lane];
            #pragma unroll
            for (int o = 1; o < 32; o <<= 1) {
                int y = __shfl_up_sync(0xffffffffu, v, o);
                if (lane >= o) v += y;
            }
            wsum[lane] = v;
        }
        __syncthreads();
        int incl = x + ((w > 0) ? wsum[w - 1] : 0) + carry;
        if (i < NN) g_rowptr[i + 1] = incl;
        __syncthreads();
        if (tid == 1023) carry = incl;
        __syncthreads();
    }
}

__global__ void fill_k(const int* __restrict__ src, const int* __restrict__ dst) {
    int e = blockIdx.x * blockDim.x + threadIdx.x;
    if (e >= E2) return;
    int s, d;
    if (e < EE) { s = src[e]; d = dst[e]; } else { s = e - EE; d = s; }
    int pos = atomicAdd(&g_cur[d], 1);
    g_csrc[g_rowptr[d] + pos] = s;
}

// ---------------- attention node terms (standalone; one warp per (node,head)) ----------------
__global__ void attn_node_k(const float* __restrict__ att_s, const float* __restrict__ att_d) {
    int gw = (blockIdx.x * blockDim.x + threadIdx.x) >> 5;
    int lane = threadIdx.x & 31;
    if (gw >= NN * NH) return;
    int n = gw / NH, h = gw - n * NH;
    float2 hv = *(const float2*)&g_H[n * FF + h * HD + 2 * lane];
    float2 as = *(const float2*)&att_s[h * HD + 2 * lane];
    float2 ad = *(const float2*)&att_d[h * HD + 2 * lane];
    float ps = hv.x * as.x + hv.y * as.y;
    float pd = hv.x * ad.x + hv.y * ad.y;
    #pragma unroll
    for (int o = 16; o; o >>= 1) {
        ps += __shfl_xor_sync(0xffffffffu, ps, o);
        pd += __shfl_xor_sync(0xffffffffu, pd, o);
    }
    if (lane == 0) {
        g_asrc[gw] = ps;
        g_adst[gw] = pd;
    }
}

// ---------------- fused softmax + aggregation: one warp per (node, head) ----------------
// ev = exp(leaky_relu(asrc[s] + adst[n])) computed in-warp; max-shift is unnecessary
// (logits bounded, exp safe in fp32) and cancels in e/sum.
__global__ void aggregate_k(const float* __restrict__ bias, float* __restrict__ out, int do_relu) {
    int gw = (blockIdx.x * blockDim.x + threadIdx.x) >> 5;
    int lane = threadIdx.x & 31;
    if (gw >= NN * NH) return;
    int n = gw / NH, h = gw - n * NH;
    int beg = g_rowptr[n], end = g_rowptr[n + 1];
    float adst_n = g_adst[n * NH + h];
    int col = h * HD + 2 * lane;
    float ax = 0.f, ay = 0.f, ssum = 0.f;
    for (int base = beg; base < end; base += 32) {
        int idx = base + lane;
        int s = 0; float ev = 0.f;
        if (idx < end) {
            s = g_csrc[idx];
            float l = g_asrc[s * NH + h] + adst_n;
            l = (l > 0.f) ? l : 0.2f * l;
            ev = __expf(l);
        }
        int cnt = min(32, end - base);
        for (int j = 0; j < cnt; j++) {
            int sj   = __shfl_sync(0xffffffffu, s, j);
            float ej = __shfl_sync(0xffffffffu, ev, j);
            float2 v = *(const float2*)&g_H[sj * FF + col];
            ssum += ej;
            ax += ej * v.x;
            ay += ej * v.y;
        }
    }
    float inv = 1.0f / ssum;
    ax = ax * inv + bias[col];
    ay = ay * inv + bias[col + 1];
    if (do_relu) { ax = fmaxf(ax, 0.f); ay = fmaxf(ay, 0.f); }
    *(float2*)&out[n * FF + col] = make_float2(ax, ay);
}

// ---------------- launcher ----------------
extern "C" void kernel_launch(void* const* d_in, const int* in_sizes, int n_in,
                              void* d_out, int out_size)
{
    const float* x    = (const float*)d_in[0];
    const int*   ei   = (const int*)  d_in[1];
    const float* W1   = (const float*)d_in[2];
    const float* as1  = (const float*)d_in[3];
    const float* ad1  = (const float*)d_in[4];
    const float* b1   = (const float*)d_in[5];
    const float* W2   = (const float*)d_in[6];
    const float* as2  = (const float*)d_in[7];
    const float* ad2  = (const float*)d_in[8];
    const float* b2   = (const float*)d_in[9];
    const float* Wout = (const float*)d_in[10];
    const float* bout = (const float*)d_in[11];
    float* out = (float*)d_out;

    const int* src = ei;
    const int* dst = ei + EE;

    void* p;
    cudaGetSymbolAddress(&p, g_H); float* pH = (float*)p;
    cudaGetSymbolAddress(&p, g_X); float* pX = (float*)p;

    const int EB = (E2 + 255) / 256;
    const int NB = (NN + 255) / 256;
    const int WB = (NN * NH * 32 + 255) / 256;
    const int GB = (NN + 127) / 128;

    // CSR build (shared by both layers)
    zero_nodes<<<NB, 256>>>();
    hist_k<<<EB, 256>>>(dst);
    scan_k<<<1, 1024>>>();
    fill_k<<<EB, 256>>>(src, dst);

    // ---- layer 1 ----
    gemm_mma_k<<<dim3(GB, FF / 64), 256>>>(x, W1, pH, NN, F0, FF, nullptr);
    attn_node_k<<<WB, 256>>>(as1, ad1);
    aggregate_k<<<WB, 256>>>(b1, pX, 1);

    // ---- layer 2 ----
    gemm_mma_k<<<dim3(GB, FF / 64), 256>>>(pX, W2, pH, NN, FF, FF, nullptr);
    attn_node_k<<<WB, 256>>>(as2, ad2);
    aggregate_k<<<WB, 256>>>(b2, pX, 1);

    // ---- readout ----
    gemm_mma_k<<<dim3(GB, 1), 256>>>(pX, Wout, out, NN, FF, NC, bout);
}

// round 16
// speedup vs baseline: 1.4275x; 1.4275x over previous
#include <cuda_runtime.h>
#include <cstdint>

#define NN 50000
#define EE 800000
#define E2 (EE + NN)
#define F0 256
#define FF 192
#define NH 3
#define HD 64
#define NC 40
#define SB 196                 // scan blocks: ceil(NN/256)

// ---------------- static device scratch ----------------
__device__ __align__(128) float    g_H[NN * FF];
__device__ __align__(128) float    g_X[NN * FF];
__device__ float    g_asrc[NN * NH];
__device__ float    g_adst[NN * NH];
__device__ float    g_sum[NN * NH];
__device__ __align__(128) float    g_ee[E2 * NH];
__device__ int      g_deg[NN];
__device__ int      g_cur[NN];
__device__ int      g_rowptr[NN + 1];
__device__ int      g_csrc[E2];
__device__ int      g_ceid[E2];
__device__ int      g_bsum[SB];
__device__ int      g_boff[SB];

// ---------------- helpers ----------------
__device__ __forceinline__ uint32_t s2u(const void* p) {
    uint32_t a;
    asm("{ .reg .u64 t; cvta.to.shared.u64 t, %1; cvt.u32.u64 %0, t; }" : "=r"(a) : "l"(p));
    return a;
}
__device__ __forceinline__ void cp16(uint32_t s, const void* g) {
    asm volatile("cp.async.cg.shared.global [%0], [%1], 16;" :: "r"(s), "l"(g));
}
__device__ __forceinline__ void cp16z(uint32_t s, const void* g, int valid) {
    asm volatile("cp.async.cg.shared.global [%0], [%1], 16, %2;" :: "r"(s), "l"(g), "r"(valid));
}
__device__ __forceinline__ void cp_commit() { asm volatile("cp.async.commit_group;" ::: "memory"); }
template<int NPEND> __device__ __forceinline__ void cp_wait() {
    asm volatile("cp.async.wait_group %0;" :: "n"(NPEND) : "memory");
}
__device__ __forceinline__ uint32_t f2tf(float f) {
    uint32_t r;
    asm("cvt.rna.tf32.f32 %0, %1;" : "=r"(r) : "f"(f));
    return r;
}
__device__ __forceinline__ void mma_tf32(float* c, const uint32_t* a, const uint32_t* b) {
    asm volatile(
        "mma.sync.aligned.m16n8k8.row.col.f32.tf32.tf32.f32 "
        "{%0,%1,%2,%3}, {%4,%5,%6,%7}, {%8,%9}, {%0,%1,%2,%3};"
        : "+f"(c[0]), "+f"(c[1]), "+f"(c[2]), "+f"(c[3])
        : "r"(a[0]), "r"(a[1]), "r"(a[2]), "r"(a[3]), "r"(b[0]), "r"(b[1]));
}

// ---------------- tf32 mma.sync GEMM (identical to round-6 best) ----------------
#define AST 20
#define BST 72

__global__ void __launch_bounds__(256) gemm_mma_k(
    const float* __restrict__ A, const float* __restrict__ B, float* __restrict__ C,
    int M, int K, int N, const float* __restrict__ bias)
{
    __shared__ float As[2][128 * AST];
    __shared__ float Bs[2][16 * BST];

    int tid = threadIdx.x, wid = tid >> 5, lane = tid & 31;
    int warp_m = wid & 3, warp_n = wid >> 2;
    int m0 = blockIdx.x * 128, n0 = blockIdx.y * 64;
    int gid = lane >> 2, tig = lane & 3;

    float acc[2][4][4];
    #pragma unroll
    for (int i = 0; i < 2; i++)
        #pragma unroll
        for (int j = 0; j < 4; j++)
            #pragma unroll
            for (int t = 0; t < 4; t++) acc[i][j][t] = 0.f;

    uint32_t asb[2] = { s2u(As[0]), s2u(As[1]) };
    uint32_t bsb[2] = { s2u(Bs[0]), s2u(Bs[1]) };

    auto prefetch = [&](int st, int kt) {
        int k0 = kt * 16;
        #pragma unroll
        for (int i = 0; i < 2; i++) {
            int idx = tid + i * 256;
            int m = idx >> 2, ch = idx & 3;
            int grow = m0 + m; if (grow >= M) grow = M - 1;
            cp16(asb[st] + (uint32_t)(m * AST + ch * 4) * 4u,
                 A + (size_t)grow * K + k0 + ch * 4);
        }
        {
            int k = tid >> 4, ch = tid & 15;
            int col = n0 + ch * 4;
            int valid = (N - col) * 4;
            if (valid > 16) valid = 16;
            if (valid < 0) valid = 0;
            const float* src = B + (size_t)(k0 + k) * N + (valid > 0 ? col : 0);
            cp16z(bsb[st] + (uint32_t)(k * BST + ch * 4) * 4u, src, valid);
        }
    };

    int KT = K >> 4;
    prefetch(0, 0); cp_commit();
    prefetch(1, 1); cp_commit();

    for (int kt = 0; kt < KT; kt++) {
        int st = kt & 1;
        if (kt + 1 < KT) cp_wait<1>(); else cp_wait<0>();
        __syncthreads();

        const float* as = As[st];
        const float* bs = Bs[st];
        #pragma unroll
        for (int ks = 0; ks < 2; ks++) {
            int kk = ks * 8;
            uint32_t af[2][4], bf[4][2];
            #pragma unroll
            for (int mt = 0; mt < 2; mt++) {
                int r = warp_m * 32 + mt * 16 + gid;
                af[mt][0] = f2tf(as[r * AST + kk + tig]);
                af[mt][1] = f2tf(as[(r + 8) * AST + kk + tig]);
                af[mt][2] = f2tf(as[r * AST + kk + tig + 4]);
                af[mt][3] = f2tf(as[(r + 8) * AST + kk + tig + 4]);
            }
            #pragma unroll
            for (int nt = 0; nt < 4; nt++) {
                int c = warp_n * 32 + nt * 8 + gid;
                bf[nt][0] = f2tf(bs[(kk + tig) * BST + c]);
                bf[nt][1] = f2tf(bs[(kk + tig + 4) * BST + c]);
            }
            #pragma unroll
            for (int mt = 0; mt < 2; mt++)
                #pragma unroll
                for (int nt = 0; nt < 4; nt++)
                    mma_tf32(acc[mt][nt], af[mt], bf[nt]);
        }
        __syncthreads();
        if (kt + 2 < KT) { prefetch(st, kt + 2); cp_commit(); }
    }

    #pragma unroll
    for (int mt = 0; mt < 2; mt++) {
        #pragma unroll
        for (int nt = 0; nt < 4; nt++) {
            int col = n0 + warp_n * 32 + nt * 8 + tig * 2;
            if (col >= N) continue;
            float bx = 0.f, by = 0.f;
            if (bias) { bx = bias[col]; by = bias[col + 1]; }
            int r0 = m0 + warp_m * 32 + mt * 16 + gid;
            if (r0 < M)
                *(float2*)&C[(size_t)r0 * N + col] =
                    make_float2(acc[mt][nt][0] + bx, acc[mt][nt][1] + by);
            int r1 = r0 + 8;
            if (r1 < M)
                *(float2*)&C[(size_t)r1 * N + col] =
                    make_float2(acc[mt][nt][2] + bx, acc[mt][nt][3] + by);
        }
    }
}

// ---------------- CSR build ----------------
__global__ void hist_k(const int* __restrict__ dst) {
    int e = blockIdx.x * blockDim.x + threadIdx.x;
    if (e >= E2) return;
    int d = (e < EE) ? dst[e] : (e - EE);
    atomicAdd(&g_deg[d], 1);
}

// parallel scan: stage 1 — per-block sums of 256 degrees
__global__ void __launch_bounds__(256) scan1_k() {
    __shared__ int ws[8];
    int i = blockIdx.x * 256 + threadIdx.x;
    int lane = threadIdx.x & 31, w = threadIdx.x >> 5;
    int x = (i < NN) ? g_deg[i] : 0;
    int v = x;
    #pragma unroll
    for (int o = 16; o; o >>= 1) v += __shfl_xor_sync(0xffffffffu, v, o);
    if (lane == 0) ws[w] = v;
    __syncthreads();
    if (threadIdx.x == 0) {
        int t = 0;
        #pragma unroll
        for (int k = 0; k < 8; k++) t += ws[k];
        g_bsum[blockIdx.x] = t;
    }
}

// stage 2 — exclusive scan of SB block sums (single block)
__global__ void __launch_bounds__(256) scan2_k() {
    __shared__ int ws[8];
    int tid = threadIdx.x, lane = tid & 31, w = tid >> 5;
    int x = (tid < SB) ? g_bsum[tid] : 0;
    int incl = x;
    #pragma unroll
    for (int o = 1; o < 32; o <<= 1) {
        int y = __shfl_up_sync(0xffffffffu, incl, o);
        if (lane >= o) incl += y;
    }
    if (lane == 31) ws[w] = incl;
    __syncthreads();
    if (w == 0 && lane < 8) {
        int v = ws[lane];
        #pragma unroll
        for (int o = 1; o < 8; o <<= 1) {
            int y = __shfl_up_sync(0xffu, v, o);
            if (lane >= o) v += y;
        }
        ws[lane] = v;
    }
    __syncthreads();
    int off = incl - x + ((w > 0) ? ws[w - 1] : 0);
    if (tid < SB) g_boff[tid] = off;
}

// stage 3 — expand: rowptr[i] = boff[b] + exclusive-scan within block
__global__ void __launch_bounds__(256) scan3_k() {
    __shared__ int ws[8];
    int i = blockIdx.x * 256 + threadIdx.x;
    int lane = threadIdx.x & 31, w = threadIdx.x >> 5;
    int x = (i < NN) ? g_deg[i] : 0;
    int incl = x;
    #pragma unroll
    for (int o = 1; o < 32; o <<= 1) {
        int y = __shfl_up_sync(0xffffffffu, incl, o);
        if (lane >= o) incl += y;
    }
    if (lane == 31) ws[w] = incl;
    __syncthreads();
    if (w == 0 && lane < 8) {
        int v = ws[lane];
        #pragma unroll
        for (int o = 1; o < 8; o <<= 1) {
            int y = __shfl_up_sync(0xffu, v, o);
            if (lane >= o) v += y;
        }
        ws[lane] = v;
    }
    __syncthreads();
    int excl = incl - x + ((w > 0) ? ws[w - 1] : 0) + g_boff[blockIdx.x];
    if (i < NN) g_rowptr[i] = excl;
    if (i == NN - 1) g_rowptr[NN] = excl + x;
}

__global__ void fill_k(const int* __restrict__ src, const int* __restrict__ dst) {
    int e = blockIdx.x * blockDim.x + threadIdx.x;
    if (e >= E2) return;
    int s, d;
    if (e < EE) { s = src[e]; d = dst[e]; } else { s = e - EE; d = s; }
    int pos = atomicAdd(&g_cur[d], 1);
    int at = g_rowptr[d] + pos;
    g_csrc[at] = s;
    g_ceid[at] = e;
}

// ---------------- attention node terms ----------------
__global__ void attn_node_k(const float* __restrict__ att_s, const float* __restrict__ att_d) {
    int gw = (blockIdx.x * blockDim.x + threadIdx.x) >> 5;
    int lane = threadIdx.x & 31;
    if (gw >= NN * NH) return;
    int n = gw / NH, h = gw - n * NH;
    float2 hv = *(const float2*)&g_H[n * FF + h * HD + 2 * lane];
    float2 as = *(const float2*)&att_s[h * HD + 2 * lane];
    float2 ad = *(const float2*)&att_d[h * HD + 2 * lane];
    float ps = hv.x * as.x + hv.y * as.y;
    float pd = hv.x * ad.x + hv.y * ad.y;
    #pragma unroll
    for (int o = 16; o; o >>= 1) {
        ps += __shfl_xor_sync(0xffffffffu, ps, o);
        pd += __shfl_xor_sync(0xffffffffu, pd, o);
    }
    if (lane == 0) {
        g_asrc[gw] = ps;
        g_adst[gw] = pd;
    }
}

// ---------------- edge pass: exp (no max shift; logits bounded) + segment sum ----------------
__global__ void edge_exp_k(const int* __restrict__ src, const int* __restrict__ dst) {
    int e = blockIdx.x * blockDim.x + threadIdx.x;
    if (e >= E2) return;
    int s, d;
    if (e < EE) { s = src[e]; d = dst[e]; } else { s = e - EE; d = s; }
    #pragma unroll
    for (int h = 0; h < NH; h++) {
        float l = g_asrc[s * NH + h] + g_adst[d * NH + h];
        l = (l > 0.f) ? l : 0.2f * l;
        float ev = __expf(l);
        g_ee[e * NH + h] = ev;
        atomicAdd(&g_sum[d * NH + h], ev);
    }
}

// ---------------- aggregation: gather via CSR, one warp per (node, head) ----------------
__global__ void aggregate_k(const float* __restrict__ bias, float* __restrict__ out, int do_relu) {
    int gw = (blockIdx.x * blockDim.x + threadIdx.x) >> 5;
    int lane = threadIdx.x & 31;
    if (gw >= NN * NH) return;
    int n = gw / NH, h = gw - n * NH;
    int beg = g_rowptr[n], end = g_rowptr[n + 1];
    float inv = 1.0f / g_sum[gw];
    int col = h * HD + 2 * lane;
    float ax = 0.f, ay = 0.f;
    for (int base = beg; base < end; base += 32) {
        int idx = base + lane;
        int s = 0; float ev = 0.f;
        if (idx < end) {
            s = g_csrc[idx];
            ev = g_ee[g_ceid[idx] * NH + h];
        }
        int cnt = min(32, end - base);
        for (int j = 0; j < cnt; j++) {
            int sj   = __shfl_sync(0xffffffffu, s, j);
            float ej = __shfl_sync(0xffffffffu, ev, j);
            float2 v = *(const float2*)&g_H[sj * FF + col];
            ax += ej * v.x;
            ay += ej * v.y;
        }
    }
    ax = ax * inv + bias[col];
    ay = ay * inv + bias[col + 1];
    if (do_relu) { ax = fmaxf(ax, 0.f); ay = fmaxf(ay, 0.f); }
    *(float2*)&out[n * FF + col] = make_float2(ax, ay);
}

// ---------------- launcher ----------------
extern "C" void kernel_launch(void* const* d_in, const int* in_sizes, int n_in,
                              void* d_out, int out_size)
{
    const float* x    = (const float*)d_in[0];
    const int*   ei   = (const int*)  d_in[1];
    const float* W1   = (const float*)d_in[2];
    const float* as1  = (const float*)d_in[3];
    const float* ad1  = (const float*)d_in[4];
    const float* b1   = (const float*)d_in[5];
    const float* W2   = (const float*)d_in[6];
    const float* as2  = (const float*)d_in[7];
    const float* ad2  = (const float*)d_in[8];
    const float* b2   = (const float*)d_in[9];
    const float* Wout = (const float*)d_in[10];
    const float* bout = (const float*)d_in[11];
    float* out = (float*)d_out;

    const int* src = ei;
    const int* dst = ei + EE;

    void* p;
    cudaGetSymbolAddress(&p, g_H);   float* pH   = (float*)p;
    cudaGetSymbolAddress(&p, g_X);   float* pX   = (float*)p;
    cudaGetSymbolAddress(&p, g_deg); void*  pDeg = p;
    cudaGetSymbolAddress(&p, g_cur); void*  pCur = p;
    cudaGetSymbolAddress(&p, g_sum); void*  pSum = p;

    const int EB = (E2 + 255) / 256;
    const int WB = (NN * NH * 32 + 255) / 256;
    const int GB = (NN + 127) / 128;

    // CSR build (shared by both layers)
    cudaMemsetAsync(pDeg, 0, NN * sizeof(int), 0);
    cudaMemsetAsync(pCur, 0, NN * sizeof(int), 0);
    hist_k<<<EB, 256>>>(dst);
    scan1_k<<<SB, 256>>>();
    scan2_k<<<1, 256>>>();
    scan3_k<<<SB, 256>>>();
    fill_k<<<EB, 256>>>(src, dst);

    // ---- layer 1 ----
    gemm_mma_k<<<dim3(GB, FF / 64), 256>>>(x, W1, pH, NN, F0, FF, nullptr);
    cudaMemsetAsync(pSum, 0, NN * NH * sizeof(float), 0);
    attn_node_k<<<WB, 256>>>(as1, ad1);
    edge_exp_k<<<EB, 256>>>(src, dst);
    aggregate_k<<<WB, 256>>>(b1, pX, 1);

    // ---- layer 2 ----
    gemm_mma_k<<<dim3(GB, FF / 64), 256>>>(pX, W2, pH, NN, FF, FF, nullptr);
    cudaMemsetAsync(pSum, 0, NN * NH * sizeof(float), 0);
    attn_node_k<<<WB, 256>>>(as2, ad2);
    edge_exp_k<<<EB, 256>>>(src, dst);
    aggregate_k<<<WB, 256>>>(b2, pX, 1);

    // ---- readout ----
    gemm_mma_k<<<dim3(GB, 1), 256>>>(pX, Wout, out, NN, FF, NC, bout);
}

// round 17
// speedup vs baseline: 1.4940x; 1.0466x over previous
#include <cuda_runtime.h>
#include <cuda_fp16.h>
#include <cstdint>

#define NN 50000
#define EE 800000
#define E2 (EE + NN)
#define F0 256
#define FF 192
#define FH 96                  // FF/2 half2 per node
#define NH 3
#define HD 64
#define NC 40
#define SB 196                 // scan blocks: ceil(NN/256)

// ---------------- static device scratch ----------------
__device__ __align__(128) __half2 g_Hh[NN * FH];   // fp16 features (pre-aggregation)
__device__ __align__(128) float   g_X[NN * FF];    // layer output (fp32, feeds next GEMM)
__device__ float    g_asrc[NN * NH];
__device__ float    g_adst[NN * NH];
__device__ __align__(128) float   g_ee[NH * E2];   // exp(logit), CSR slot order, per head plane
__device__ int      g_deg[NN];
__device__ int      g_cur[NN];
__device__ int      g_rowptr[NN + 1];
__device__ int      g_csrc[E2];
__device__ int      g_cdst[E2];
__device__ int      g_bsum[SB];
__device__ int      g_boff[SB];

// ---------------- helpers ----------------
__device__ __forceinline__ uint32_t s2u(const void* p) {
    uint32_t a;
    asm("{ .reg .u64 t; cvta.to.shared.u64 t, %1; cvt.u32.u64 %0, t; }" : "=r"(a) : "l"(p));
    return a;
}
__device__ __forceinline__ void cp16(uint32_t s, const void* g) {
    asm volatile("cp.async.cg.shared.global [%0], [%1], 16;" :: "r"(s), "l"(g));
}
__device__ __forceinline__ void cp16z(uint32_t s, const void* g, int valid) {
    asm volatile("cp.async.cg.shared.global [%0], [%1], 16, %2;" :: "r"(s), "l"(g), "r"(valid));
}
__device__ __forceinline__ void cp_commit() { asm volatile("cp.async.commit_group;" ::: "memory"); }
template<int NPEND> __device__ __forceinline__ void cp_wait() {
    asm volatile("cp.async.wait_group %0;" :: "n"(NPEND) : "memory");
}
__device__ __forceinline__ uint32_t f2tf(float f) {
    uint32_t r;
    asm("cvt.rna.tf32.f32 %0, %1;" : "=r"(r) : "f"(f));
    return r;
}
__device__ __forceinline__ void mma_tf32(float* c, const uint32_t* a, const uint32_t* b) {
    asm volatile(
        "mma.sync.aligned.m16n8k8.row.col.f32.tf32.tf32.f32 "
        "{%0,%1,%2,%3}, {%4,%5,%6,%7}, {%8,%9}, {%0,%1,%2,%3};"
        : "+f"(c[0]), "+f"(c[1]), "+f"(c[2]), "+f"(c[3])
        : "r"(a[0]), "r"(a[1]), "r"(a[2]), "r"(a[3]), "r"(b[0]), "r"(b[1]));
}

// ---------------- tf32 mma.sync GEMM ----------------
// Same mainloop as the measured-best round-6 kernel. Epilogue: if Ch != null,
// store half2 features (layer GEMMs); else store fp32 (+bias) (readout GEMM).
#define AST 20
#define BST 72

__global__ void __launch_bounds__(256) gemm_mma_k(
    const float* __restrict__ A, const float* __restrict__ B, float* __restrict__ C,
    __half2* __restrict__ Ch,
    int M, int K, int N, const float* __restrict__ bias)
{
    __shared__ float As[2][128 * AST];
    __shared__ float Bs[2][16 * BST];

    int tid = threadIdx.x, wid = tid >> 5, lane = tid & 31;
    int warp_m = wid & 3, warp_n = wid >> 2;
    int m0 = blockIdx.x * 128, n0 = blockIdx.y * 64;
    int gid = lane >> 2, tig = lane & 3;

    float acc[2][4][4];
    #pragma unroll
    for (int i = 0; i < 2; i++)
        #pragma unroll
        for (int j = 0; j < 4; j++)
            #pragma unroll
            for (int t = 0; t < 4; t++) acc[i][j][t] = 0.f;

    uint32_t asb[2] = { s2u(As[0]), s2u(As[1]) };
    uint32_t bsb[2] = { s2u(Bs[0]), s2u(Bs[1]) };

    auto prefetch = [&](int st, int kt) {
        int k0 = kt * 16;
        #pragma unroll
        for (int i = 0; i < 2; i++) {
            int idx = tid + i * 256;
            int m = idx >> 2, ch = idx & 3;
            int grow = m0 + m; if (grow >= M) grow = M - 1;
            cp16(asb[st] + (uint32_t)(m * AST + ch * 4) * 4u,
                 A + (size_t)grow * K + k0 + ch * 4);
        }
        {
            int k = tid >> 4, ch = tid & 15;
            int col = n0 + ch * 4;
            int valid = (N - col) * 4;
            if (valid > 16) valid = 16;
            if (valid < 0) valid = 0;
            const float* src = B + (size_t)(k0 + k) * N + (valid > 0 ? col : 0);
            cp16z(bsb[st] + (uint32_t)(k * BST + ch * 4) * 4u, src, valid);
        }
    };

    int KT = K >> 4;
    prefetch(0, 0); cp_commit();
    prefetch(1, 1); cp_commit();

    for (int kt = 0; kt < KT; kt++) {
        int st = kt & 1;
        if (kt + 1 < KT) cp_wait<1>(); else cp_wait<0>();
        __syncthreads();

        const float* as = As[st];
        const float* bs = Bs[st];
        #pragma unroll
        for (int ks = 0; ks < 2; ks++) {
            int kk = ks * 8;
            uint32_t af[2][4], bf[4][2];
            #pragma unroll
            for (int mt = 0; mt < 2; mt++) {
                int r = warp_m * 32 + mt * 16 + gid;
                af[mt][0] = f2tf(as[r * AST + kk + tig]);
                af[mt][1] = f2tf(as[(r + 8) * AST + kk + tig]);
                af[mt][2] = f2tf(as[r * AST + kk + tig + 4]);
                af[mt][3] = f2tf(as[(r + 8) * AST + kk + tig + 4]);
            }
            #pragma unroll
            for (int nt = 0; nt < 4; nt++) {
                int c = warp_n * 32 + nt * 8 + gid;
                bf[nt][0] = f2tf(bs[(kk + tig) * BST + c]);
                bf[nt][1] = f2tf(bs[(kk + tig + 4) * BST + c]);
            }
            #pragma unroll
            for (int mt = 0; mt < 2; mt++)
                #pragma unroll
                for (int nt = 0; nt < 4; nt++)
                    mma_tf32(acc[mt][nt], af[mt], bf[nt]);
        }
        __syncthreads();
        if (kt + 2 < KT) { prefetch(st, kt + 2); cp_commit(); }
    }

    // ---- epilogue ----
    #pragma unroll
    for (int mt = 0; mt < 2; mt++) {
        #pragma unroll
        for (int nt = 0; nt < 4; nt++) {
            int col = n0 + warp_n * 32 + nt * 8 + tig * 2;
            if (col >= N) continue;
            int r0 = m0 + warp_m * 32 + mt * 16 + gid;
            int r1 = r0 + 8;
            if (Ch) {
                if (r0 < M)
                    Ch[(size_t)r0 * FH + (col >> 1)] =
                        __floats2half2_rn(acc[mt][nt][0], acc[mt][nt][1]);
                if (r1 < M)
                    Ch[(size_t)r1 * FH + (col >> 1)] =
                        __floats2half2_rn(acc[mt][nt][2], acc[mt][nt][3]);
            } else {
                float bx = 0.f, by = 0.f;
                if (bias) { bx = bias[col]; by = bias[col + 1]; }
                if (r0 < M)
                    *(float2*)&C[(size_t)r0 * N + col] =
                        make_float2(acc[mt][nt][0] + bx, acc[mt][nt][1] + by);
                if (r1 < M)
                    *(float2*)&C[(size_t)r1 * N + col] =
                        make_float2(acc[mt][nt][2] + bx, acc[mt][nt][3] + by);
            }
        }
    }
}

// ---------------- CSR build ----------------
__global__ void hist_k(const int* __restrict__ dst) {
    int e = blockIdx.x * blockDim.x + threadIdx.x;
    if (e >= E2) return;
    int d = (e < EE) ? dst[e] : (e - EE);
    atomicAdd(&g_deg[d], 1);
}

__global__ void __launch_bounds__(256) scan1_k() {
    __shared__ int ws[8];
    int i = blockIdx.x * 256 + threadIdx.x;
    int lane = threadIdx.x & 31, w = threadIdx.x >> 5;
    int x = (i < NN) ? g_deg[i] : 0;
    int v = x;
    #pragma unroll
    for (int o = 16; o; o >>= 1) v += __shfl_xor_sync(0xffffffffu, v, o);
    if (lane == 0) ws[w] = v;
    __syncthreads();
    if (threadIdx.x == 0) {
        int t = 0;
        #pragma unroll
        for (int k = 0; k < 8; k++) t += ws[k];
        g_bsum[blockIdx.x] = t;
    }
}

__global__ void __launch_bounds__(256) scan2_k() {
    __shared__ int ws[8];
    int tid = threadIdx.x, lane = tid & 31, w = tid >> 5;
    int x = (tid < SB) ? g_bsum[tid] : 0;
    int incl = x;
    #pragma unroll
    for (int o = 1; o < 32; o <<= 1) {
        int y = __shfl_up_sync(0xffffffffu, incl, o);
        if (lane >= o) incl += y;
    }
    if (lane == 31) ws[w] = incl;
    __syncthreads();
    if (w == 0 && lane < 8) {
        int v = ws[lane];
        #pragma unroll
        for (int o = 1; o < 8; o <<= 1) {
            int y = __shfl_up_sync(0xffu, v, o);
            if (lane >= o) v += y;
        }
        ws[lane] = v;
    }
    __syncthreads();
    int off = incl - x + ((w > 0) ? ws[w - 1] : 0);
    if (tid < SB) g_boff[tid] = off;
}

__global__ void __launch_bounds__(256) scan3_k() {
    __shared__ int ws[8];
    int i = blockIdx.x * 256 + threadIdx.x;
    int lane = threadIdx.x & 31, w = threadIdx.x >> 5;
    int x = (i < NN) ? g_deg[i] : 0;
    int incl = x;
    #pragma unroll
    for (int o = 1; o < 32; o <<= 1) {
        int y = __shfl_up_sync(0xffffffffu, incl, o);
        if (lane >= o) incl += y;
    }
    if (lane == 31) ws[w] = incl;
    __syncthreads();
    if (w == 0 && lane < 8) {
        int v = ws[lane];
        #pragma unroll
        for (int o = 1; o < 8; o <<= 1) {
            int y = __shfl_up_sync(0xffu, v, o);
            if (lane >= o) v += y;
        }
        ws[lane] = v;
    }
    __syncthreads();
    int excl = incl - x + ((w > 0) ? ws[w - 1] : 0) + g_boff[blockIdx.x];
    if (i < NN) g_rowptr[i] = excl;
    if (i == NN - 1) g_rowptr[NN] = excl + x;
}

__global__ void fill_k(const int* __restrict__ src, const int* __restrict__ dst) {
    int e = blockIdx.x * blockDim.x + threadIdx.x;
    if (e >= E2) return;
    int s, d;
    if (e < EE) { s = src[e]; d = dst[e]; } else { s = e - EE; d = s; }
    int pos = atomicAdd(&g_cur[d], 1);
    int at = g_rowptr[d] + pos;
    g_csrc[at] = s;
    g_cdst[at] = d;
}

// ---------------- attention node terms (fp16 features) ----------------
__global__ void attn_node_k(const float* __restrict__ att_s, const float* __restrict__ att_d) {
    int gw = (blockIdx.x * blockDim.x + threadIdx.x) >> 5;
    int lane = threadIdx.x & 31;
    if (gw >= NN * NH) return;
    int n = gw / NH, h = gw - n * NH;
    float2 hv = __half22float2(g_Hh[n * FH + h * 32 + lane]);
    float2 as = *(const float2*)&att_s[h * HD + 2 * lane];
    float2 ad = *(const float2*)&att_d[h * HD + 2 * lane];
    float ps = hv.x * as.x + hv.y * as.y;
    float pd = hv.x * ad.x + hv.y * ad.y;
    #pragma unroll
    for (int o = 16; o; o >>= 1) {
        ps += __shfl_xor_sync(0xffffffffu, ps, o);
        pd += __shfl_xor_sync(0xffffffffu, pd, o);
    }
    if (lane == 0) {
        g_asrc[gw] = ps;
        g_adst[gw] = pd;
    }
}

// ---------------- edge pass over CSR slots: ee[h][slot] = exp(leaky(logit)) ----------------
// No max shift (logits bounded, exp safe in fp32; shift cancels in e/sum).
__global__ void edge_exp_k() {
    int i = blockIdx.x * blockDim.x + threadIdx.x;
    if (i >= E2) return;
    int s = g_csrc[i];
    int d = g_cdst[i];
    #pragma unroll
    for (int h = 0; h < NH; h++) {
        float l = g_asrc[s * NH + h] + g_adst[d * NH + h];
        l = (l > 0.f) ? l : 0.2f * l;
        g_ee[h * E2 + i] = __expf(l);
    }
}

// ---------------- aggregation: gather via CSR, one warp per (node, head) ----------------
// ee reads are contiguous (CSR order); softmax sum accumulated in-warp (no g_sum).
__global__ void aggregate_k(const float* __restrict__ bias, float* __restrict__ out, int do_relu) {
    int gw = (blockIdx.x * blockDim.x + threadIdx.x) >> 5;
    int lane = threadIdx.x & 31;
    if (gw >= NN * NH) return;
    int n = gw / NH, h = gw - n * NH;
    int beg = g_rowptr[n], end = g_rowptr[n + 1];
    const float* eeh = &g_ee[h * E2];
    int hcol = h * 32 + lane;                 // half2 column
    float ax = 0.f, ay = 0.f, ssum = 0.f;
    for (int base = beg; base < end; base += 32) {
        int idx = base + lane;
        int s = 0; float ev = 0.f;
        if (idx < end) {
            s = g_csrc[idx];
            ev = eeh[idx];
        }
        int cnt = min(32, end - base);
        for (int j = 0; j < cnt; j++) {
            int sj   = __shfl_sync(0xffffffffu, s, j);
            float ej = __shfl_sync(0xffffffffu, ev, j);
            float2 v = __half22float2(g_Hh[(size_t)sj * FH + hcol]);
            ssum += ej;
            ax += ej * v.x;
            ay += ej * v.y;
        }
    }
    float inv = 1.0f / ssum;
    int col = h * HD + 2 * lane;
    ax = ax * inv + bias[col];
    ay = ay * inv + bias[col + 1];
    if (do_relu) { ax = fmaxf(ax, 0.f); ay = fmaxf(ay, 0.f); }
    *(float2*)&out[n * FF + col] = make_float2(ax, ay);
}

// ---------------- launcher ----------------
extern "C" void kernel_launch(void* const* d_in, const int* in_sizes, int n_in,
                              void* d_out, int out_size)
{
    const float* x    = (const float*)d_in[0];
    const int*   ei   = (const int*)  d_in[1];
    const float* W1   = (const float*)d_in[2];
    const float* as1  = (const float*)d_in[3];
    const float* ad1  = (const float*)d_in[4];
    const float* b1   = (const float*)d_in[5];
    const float* W2   = (const float*)d_in[6];
    const float* as2  = (const float*)d_in[7];
    const float* ad2  = (const float*)d_in[8];
    const float* b2   = (const float*)d_in[9];
    const float* Wout = (const float*)d_in[10];
    const float* bout = (const float*)d_in[11];
    float* out = (float*)d_out;

    const int* src = ei;
    const int* dst = ei + EE;

    void* p;
    cudaGetSymbolAddress(&p, g_Hh);  __half2* pHh = (__half2*)p;
    cudaGetSymbolAddress(&p, g_X);   float*   pX  = (float*)p;
    cudaGetSymbolAddress(&p, g_deg); void*    pDeg = p;
    cudaGetSymbolAddress(&p, g_cur); void*    pCur = p;

    const int EB = (E2 + 255) / 256;
    const int WB = (NN * NH * 32 + 255) / 256;
    const int GB = (NN + 127) / 128;

    // CSR build (shared by both layers)
    cudaMemsetAsync(pDeg, 0, NN * sizeof(int), 0);
    cudaMemsetAsync(pCur, 0, NN * sizeof(int), 0);
    hist_k<<<EB, 256>>>(dst);
    scan1_k<<<SB, 256>>>();
    scan2_k<<<1, 256>>>();
    scan3_k<<<SB, 256>>>();
    fill_k<<<EB, 256>>>(src, dst);

    // ---- layer 1 ----
    gemm_mma_k<<<dim3(GB, FF / 64), 256>>>(x, W1, nullptr, pHh, NN, F0, FF, nullptr);
    attn_node_k<<<WB, 256>>>(as1, ad1);
    edge_exp_k<<<EB, 256>>>();
    aggregate_k<<<WB, 256>>>(b1, pX, 1);

    // ---- layer 2 ----
    gemm_mma_k<<<dim3(GB, FF / 64), 256>>>(pX, W2, nullptr, pHh, NN, FF, FF, nullptr);
    attn_node_k<<<WB, 256>>>(as2, ad2);
    edge_exp_k<<<EB, 256>>>();
    aggregate_k<<<WB, 256>>>(b2, pX, 1);

    // ---- readout ----
    gemm_mma_k<<<dim3(GB, 1), 256>>>(pX, Wout, out, nullptr, NN, FF, NC, bout);
}